// round 7
// baseline (speedup 1.0000x reference)
#include <cuda_runtime.h>
#include <cuda_bf16.h>
#include <cstdint>
#include <cstdio>

#define E_DIM 1024
#define H_DIM 1024
#define VOC   32000
#define T_STEPS 64
#define NBLK  128          // persistent LSTM blocks

// -------- device scratch (no allocs allowed) --------
__device__ float g_X[T_STEPS * E_DIM];             // inputs per step
__device__ float g_hpub[(T_STEPS + 1) * H_DIM];    // h rows: row t = state entering step t
__device__ unsigned int g_hflag[(T_STEPS + 1) * NBLK];  // per (row, block) ready flags

__device__ __forceinline__ float sigmoidf_(float x) { return 1.f / (1.f + __expf(-x)); }
// fast tanh via MUFU ex2 path: 2*sigmoid(2x) - 1   (abs err ~1e-6)
__device__ __forceinline__ float tanhf_(float x) {
    return __fdividef(2.f, 1.f + __expf(-2.f * x)) - 1.f;
}

// =====================================================================
// K0: build X, init h row 0 + flags
// =====================================================================
__global__ void prep_kernel(const int* __restrict__ captions,
                            const float* __restrict__ features,
                            const float* __restrict__ etab) {
    int t = blockIdx.x;
    const float* src = (t == 0) ? features : (etab + (size_t)captions[t - 1] * E_DIM);
    for (int k = threadIdx.x; k < E_DIM; k += blockDim.x)
        g_X[t * E_DIM + k] = src[k];
    // block t resets flag row t+1 (rows 1..64)
    if (threadIdx.x < NBLK) g_hflag[(t + 1) * NBLK + threadIdx.x] = 0u;
    if (t == 0) {
        for (int k = threadIdx.x; k < H_DIM; k += blockDim.x) g_hpub[k] = 0.f;
        if (threadIdx.x < NBLK) g_hflag[threadIdx.x] = 1u;   // row 0 ready
    }
}

// =====================================================================
// K1: persistent LSTM — barrier-free, point-to-point flag dataflow.
// Block b owns h indices [8b, 8b+8). Thread: j=tid&7, c=tid>>3.
// =====================================================================
__global__ void __launch_bounds__(512, 1)
lstm_kernel(const float* __restrict__ Wih, const float* __restrict__ Whh,
            const float* __restrict__ bih, const float* __restrict__ bhh) {
    __shared__ float Xg_s[T_STEPS * 32];   // [t][g*8+j]
    __shared__ float partA[16][32];        // [warp][g*8+j]
    __shared__ float gsum_s[32];
    __shared__ float bias_s[32];

    const int tid = threadIdx.x;
    const int w   = tid >> 5;
    const int l   = tid & 31;
    const int j   = tid & 7;
    const int c   = tid >> 3;     // 0..63
    const int b   = blockIdx.x;
    const int jg  = b * 8 + j;

    if (tid < 32) {
        int g = tid >> 3, jj = tid & 7;
        int row = g * H_DIM + b * 8 + jj;
        bias_s[tid] = bih[row] + bhh[row];
    }
    float creg = 0.f;              // cell state (valid for tid < 8)

    float wreg[4][16];

    // ---- load W_ih slice into registers ----
#pragma unroll
    for (int g = 0; g < 4; g++) {
        const float4* p = (const float4*)(Wih + (size_t)(g * H_DIM + jg) * E_DIM + c * 16);
#pragma unroll
        for (int q = 0; q < 4; q++) {
            float4 a = p[q];
            wreg[g][4*q+0] = a.x; wreg[g][4*q+1] = a.y;
            wreg[g][4*q+2] = a.z; wreg[g][4*q+3] = a.w;
        }
    }
    __syncthreads();

    // ---- Phase A: input projections ----
    for (int t = 0; t < T_STEPS; t++) {
        float xv[16];
        {
            const float4* xp = (const float4*)(g_X + t * E_DIM + c * 16);
#pragma unroll
            for (int q = 0; q < 4; q++) {
                float4 a = xp[q];
                xv[4*q+0] = a.x; xv[4*q+1] = a.y; xv[4*q+2] = a.z; xv[4*q+3] = a.w;
            }
        }
        float part[4];
#pragma unroll
        for (int g = 0; g < 4; g++) {
            float s = 0.f;
#pragma unroll
            for (int i = 0; i < 16; i++) s = fmaf(wreg[g][i], xv[i], s);
            part[g] = s;
        }
#pragma unroll
        for (int g = 0; g < 4; g++) {
            part[g] += __shfl_xor_sync(0xffffffffu, part[g], 8);
            part[g] += __shfl_xor_sync(0xffffffffu, part[g], 16);
        }
        if (l < 8) {
#pragma unroll
            for (int g = 0; g < 4; g++) partA[w][g * 8 + l] = part[g];
        }
        __syncthreads();
        if (tid < 32) {
            float s = 0.f;
#pragma unroll
            for (int ww = 0; ww < 16; ww++) s += partA[ww][tid];
            Xg_s[t * 32 + tid] = s;
        }
        __syncthreads();
    }

    // ---- swap registers to W_hh slice ----
#pragma unroll
    for (int g = 0; g < 4; g++) {
        const float4* p = (const float4*)(Whh + (size_t)(g * H_DIM + jg) * H_DIM + c * 16);
#pragma unroll
        for (int q = 0; q < 4; q++) {
            float4 a = p[q];
            wreg[g][4*q+0] = a.x; wreg[g][4*q+1] = a.y;
            wreg[g][4*q+2] = a.z; wreg[g][4*q+3] = a.w;
        }
    }
    __syncthreads();

    // ---- Phase B: recurrence, flag-based dataflow ----
    for (int t = 0; t < T_STEPS; t++) {
        // wait for THIS thread's two h-producers (blocks 2c, 2c+1) of row t
        {
            const unsigned int* fl = &g_hflag[t * NBLK + 2 * c];
            unsigned int v;
            do {
                asm volatile("ld.acquire.gpu.u32 %0, [%1];"
                             : "=r"(v) : "l"(fl) : "memory");
            } while (!v);
            do {
                asm volatile("ld.acquire.gpu.u32 %0, [%1];"
                             : "=r"(v) : "l"(fl + 1) : "memory");
            } while (!v);
        }
        float hv[16];
        {
            const float4* hp = (const float4*)(g_hpub + t * H_DIM + c * 16);
#pragma unroll
            for (int q = 0; q < 4; q++) {
                float4 a = __ldcg(hp + q);
                hv[4*q+0] = a.x; hv[4*q+1] = a.y; hv[4*q+2] = a.z; hv[4*q+3] = a.w;
            }
        }
        float part[4];
#pragma unroll
        for (int g = 0; g < 4; g++) {
            float s = 0.f;
#pragma unroll
            for (int i = 0; i < 16; i++) s = fmaf(wreg[g][i], hv[i], s);
            part[g] = s;
        }
#pragma unroll
        for (int g = 0; g < 4; g++) {
            part[g] += __shfl_xor_sync(0xffffffffu, part[g], 8);
            part[g] += __shfl_xor_sync(0xffffffffu, part[g], 16);
        }
        if (l < 8) {
#pragma unroll
            for (int g = 0; g < 4; g++) partA[w][g * 8 + l] = part[g];
        }
        __syncthreads();
        if (tid < 32) {
            float s = 0.f;
#pragma unroll
            for (int ww = 0; ww < 16; ww++) s += partA[ww][tid];
            gsum_s[tid] = s + Xg_s[t * 32 + tid] + bias_s[tid];
        }
        __syncthreads();
        if (tid < 8) {
            float ii = sigmoidf_(gsum_s[tid]);
            float ff = sigmoidf_(gsum_s[8  + tid]);
            float gg = tanhf_   (gsum_s[16 + tid]);
            float oo = sigmoidf_(gsum_s[24 + tid]);
            float cc = ff * creg + ii * gg;
            creg = cc;
            float hn = oo * tanhf_(cc);

            // gather 8 h values into lane 0, publish + release flag
            float vv[8];
#pragma unroll
            for (int i = 0; i < 8; i++)
                vv[i] = __shfl_sync(0x000000FFu, hn, i, 8);
            if (tid == 0) {
                float4* dst = (float4*)(g_hpub + (t + 1) * H_DIM + b * 8);
                dst[0] = make_float4(vv[0], vv[1], vv[2], vv[3]);
                dst[1] = make_float4(vv[4], vv[5], vv[6], vv[7]);
                asm volatile("st.release.gpu.u32 [%0], %1;"
                             :: "l"(&g_hflag[(t + 1) * NBLK + b]), "r"(1u) : "memory");
            }
        }
        // NOTE: no global barrier. smem reuse across steps is protected by
        // the two __syncthreads above (writers of step t+1 cannot pass
        // sync1(t+1) until all readers of step t reached it).
    }
}

// =====================================================================
// K2: fc GEMM — fused convert + bf16 mma.sync 3-pass split (round-5 core).
// B tile reads g_hpub rows 1..64 (the per-step h outputs).
// =====================================================================
#define FC_M    128
#define FC_NCH  16

#define FCO_AF32(b) ((b) * 32768)
#define FCO_AHI     65536
#define FCO_ALO     81920
#define FCO_BHI     98304
#define FCO_BLO     106496
#define FC_SMEM     114688      // 112 KB -> 2 CTAs/SM

#define SWZ(x) ((x) ^ (((x) >> 3) & 0x70))

__device__ __forceinline__ uint32_t smem_u32(const void* p) {
    uint32_t a;
    asm("{ .reg .u64 t; cvta.to.shared.u64 t, %1; cvt.u32.u64 %0, t; }" : "=r"(a) : "l"(p));
    return a;
}

__device__ __forceinline__ void split2(float2 a, uint32_t& hi, uint32_t& lo) {
    __nv_bfloat162 h = __float22bfloat162_rn(a);
    float2 f = __bfloat1622float2(h);
    __nv_bfloat162 l2 = __float22bfloat162_rn(make_float2(a.x - f.x, a.y - f.y));
    hi = *reinterpret_cast<uint32_t*>(&h);
    lo = *reinterpret_cast<uint32_t*>(&l2);
}

#define CP16(dst, src) \
    asm volatile("cp.async.cg.shared.global [%0], [%1], 16;" :: "r"(dst), "l"(src) : "memory")
#define CP_COMMIT() asm volatile("cp.async.commit_group;" ::: "memory")
#define CP_WAIT(n)  asm volatile("cp.async.wait_group %0;" :: "n"(n) : "memory")

#define LDM_X4(r, a)                                                          \
    asm volatile("ldmatrix.sync.aligned.m8n8.x4.shared.b16 {%0,%1,%2,%3}, [%4];" \
        : "=r"((r)[0]), "=r"((r)[1]), "=r"((r)[2]), "=r"((r)[3]) : "r"(a))

#define MMA16816(d, a, b0, b1)                                                \
    asm volatile("mma.sync.aligned.m16n8k16.row.col.f32.bf16.bf16.f32 "       \
        "{%0,%1,%2,%3},{%4,%5,%6,%7},{%8,%9},{%0,%1,%2,%3};"                  \
        : "+f"((d)[0]), "+f"((d)[1]), "+f"((d)[2]), "+f"((d)[3])              \
        : "r"((a)[0]), "r"((a)[1]), "r"((a)[2]), "r"((a)[3]),                 \
          "r"(b0), "r"(b1))

__global__ void __launch_bounds__(128, 2)
fc_mma_kernel(const float* __restrict__ fcW, const float* __restrict__ fcb,
              float* __restrict__ out) {
    extern __shared__ __align__(1024) char smem[];
    const uint32_t sb = smem_u32(smem);

    const int tid  = threadIdx.x;
    const int wid  = tid >> 5;
    const int lane = tid & 31;
    const int vbase = blockIdx.x * FC_M;
    const int m0 = wid * 32;

    const int a_row  = m0 + (lane & 15);
    const uint32_t a_roff = (uint32_t)a_row * 128;
    const uint32_t a_xor  = (uint32_t)(a_row & 7) << 4;
    const uint32_t a_kh   = (uint32_t)(lane >> 4) * 16;
    const int b_rsub = (lane & 7) + ((lane >> 4) & 1) * 8;
    const uint32_t b_xor = (uint32_t)(lane & 7) << 4;
    const uint32_t b_kh  = (uint32_t)((lane >> 3) & 1) * 16;

    float acc[2][8][4];
#pragma unroll
    for (int mt = 0; mt < 2; mt++)
#pragma unroll
        for (int nt = 0; nt < 8; nt++)
#pragma unroll
            for (int q = 0; q < 4; q++) acc[mt][nt][q] = 0.f;

    auto issue = [&](int c) {
        const uint32_t dbase = sb + FCO_AF32(c & 1);
#pragma unroll
        for (int p = 0; p < 16; p++) {
            int idx = tid + p * 128;
            int row = idx >> 4, seg = idx & 15;
            const char* src = (const char*)(fcW + (size_t)(vbase + row) * E_DIM + c * 64)
                              + seg * 16;
            CP16(dbase + (uint32_t)(row * 256 + seg * 16), src);
        }
        CP_COMMIT();
    };

    issue(0);
    issue(1);

    for (int c = 0; c < FC_NCH; c++) {
        if (c < FC_NCH - 1) { CP_WAIT(1); } else { CP_WAIT(0); }
        __syncthreads();

        {
            const char* af = smem + FCO_AF32(c & 1);
#pragma unroll
            for (int p = 0; p < 32; p++) {
                int fidx = tid + p * 128;
                int row = fidx >> 5, kp = fidx & 31;
                float2 a = *(const float2*)(af + row * 256 + kp * 8);
                uint32_t hi, lo; split2(a, hi, lo);
                uint32_t off = SWZ((uint32_t)(row * 128 + kp * 4));
                *(uint32_t*)(smem + FCO_AHI + off) = hi;
                *(uint32_t*)(smem + FCO_ALO + off) = lo;
            }
        }
        {
#pragma unroll
            for (int p = 0; p < 16; p++) {
                int fidx = tid + p * 128;
                int row = fidx >> 5, kp = fidx & 31;
                float2 a = *(const float2*)(g_hpub + (row + 1) * H_DIM + c * 64 + kp * 2);
                uint32_t hi, lo; split2(a, hi, lo);
                uint32_t off = SWZ((uint32_t)(row * 128 + kp * 4));
                *(uint32_t*)(smem + FCO_BHI + off) = hi;
                *(uint32_t*)(smem + FCO_BLO + off) = lo;
            }
        }
        __syncthreads();

        if (c + 2 < FC_NCH) issue(c + 2);

        const uint32_t sAhi = sb + FCO_AHI, sAlo = sb + FCO_ALO;
        const uint32_t sBhi = sb + FCO_BHI, sBlo = sb + FCO_BLO;
#pragma unroll
        for (int ks = 0; ks < 4; ks++) {
            const uint32_t akb = (uint32_t)(ks * 32) + a_kh;
            const uint32_t bkb = (uint32_t)(ks * 32) + b_kh;

            uint32_t ah[2][4], al[2][4];
#pragma unroll
            for (int mt = 0; mt < 2; mt++) {
                uint32_t off = a_roff + (uint32_t)(mt * 16 * 128) + (akb ^ a_xor);
                LDM_X4(ah[mt], sAhi + off);
                LDM_X4(al[mt], sAlo + off);
            }
            uint32_t bh[4][4], bl[4][4];
#pragma unroll
            for (int bp = 0; bp < 4; bp++) {
                uint32_t n = (uint32_t)(bp * 16 + b_rsub);
                uint32_t off = n * 128 + (bkb ^ b_xor);
                LDM_X4(bh[bp], sBhi + off);
                LDM_X4(bl[bp], sBlo + off);
            }
#pragma unroll
            for (int mt = 0; mt < 2; mt++)
#pragma unroll
                for (int nt = 0; nt < 8; nt++) {
                    const int bp = nt >> 1, sel = (nt & 1) * 2;
                    MMA16816(acc[mt][nt], ah[mt], bh[bp][sel], bh[bp][sel + 1]);
                    MMA16816(acc[mt][nt], al[mt], bh[bp][sel], bh[bp][sel + 1]);
                    MMA16816(acc[mt][nt], ah[mt], bl[bp][sel], bl[bp][sel + 1]);
                }
        }
    }

    const int g  = lane >> 2;
    const int t4 = lane & 3;
#pragma unroll
    for (int mt = 0; mt < 2; mt++) {
        int v0 = vbase + m0 + mt * 16 + g;
        float bv0 = fcb[v0];
        float bv8 = fcb[v0 + 8];
#pragma unroll
        for (int nt = 0; nt < 8; nt++) {
            int t0 = nt * 8 + t4 * 2;
            out[(size_t)t0 * VOC + v0]           = acc[mt][nt][0] + bv0;
            out[(size_t)(t0 + 1) * VOC + v0]     = acc[mt][nt][1] + bv0;
            out[(size_t)t0 * VOC + v0 + 8]       = acc[mt][nt][2] + bv8;
            out[(size_t)(t0 + 1) * VOC + v0 + 8] = acc[mt][nt][3] + bv8;
        }
    }
}

// =====================================================================
// launch
// =====================================================================
extern "C" void kernel_launch(void* const* d_in, const int* in_sizes, int n_in,
                              void* d_out, int out_size) {
    const int*   captions = (const int*)  d_in[0];
    const float* features = (const float*)d_in[1];
    const float* etab     = (const float*)d_in[2];
    const float* W_ih     = (const float*)d_in[3];
    const float* W_hh     = (const float*)d_in[4];
    const float* b_ih     = (const float*)d_in[5];
    const float* b_hh     = (const float*)d_in[6];
    const float* fc_W     = (const float*)d_in[7];
    const float* fc_b     = (const float*)d_in[8];
    float* out = (float*)d_out;

    cudaFuncSetAttribute(fc_mma_kernel,
                         cudaFuncAttributeMaxDynamicSharedMemorySize, FC_SMEM);

    prep_kernel<<<T_STEPS, 256>>>(captions, features, etab);
    lstm_kernel<<<NBLK, 512>>>(W_ih, W_hh, b_ih, b_hh);
    fc_mma_kernel<<<VOC / FC_M, 128, FC_SMEM>>>(fc_W, fc_b, out);
}

// round 8
// speedup vs baseline: 1.3214x; 1.3214x over previous
#include <cuda_runtime.h>
#include <cuda_bf16.h>
#include <cstdint>
#include <cstdio>

#define E_DIM 1024
#define H_DIM 1024
#define VOC   32000
#define T_STEPS 64
#define NBLK  128          // persistent LSTM blocks

// -------- device scratch (no allocs allowed) --------
__device__ float g_X[T_STEPS * E_DIM];                  // inputs per step
__device__ float g_hpub[(T_STEPS + 1) * H_DIM];         // fresh h row per step
__device__ unsigned int g_hflag[(T_STEPS + 1) * NBLK];  // per (row, block) ready flags

__device__ __forceinline__ float sigmoidf_(float x) { return 1.f / (1.f + __expf(-x)); }
__device__ __forceinline__ float tanhf_(float x) {
    return __fdividef(2.f, 1.f + __expf(-2.f * x)) - 1.f;
}

// ---- packed f32x2 helpers ----
__device__ __forceinline__ void fma2(unsigned long long& d,
                                     unsigned long long a, unsigned long long b) {
    asm("fma.rn.f32x2 %0, %1, %2, %0;" : "+l"(d) : "l"(a), "l"(b));
}
__device__ __forceinline__ float sum2(unsigned long long v) {
    float lo, hi;
    asm("mov.b64 {%0, %1}, %2;" : "=f"(lo), "=f"(hi) : "l"(v));
    return lo + hi;
}
// 16B load as 2 packed f32x2 (generic / L2-bypassing variants)
__device__ __forceinline__ void ld2u64(const void* p, unsigned long long& a,
                                       unsigned long long& b) {
    asm("ld.global.v2.u64 {%0, %1}, [%2];" : "=l"(a), "=l"(b) : "l"(p));
}
__device__ __forceinline__ void ld2u64_cg(const void* p, unsigned long long& a,
                                          unsigned long long& b) {
    asm("ld.global.cg.v2.u64 {%0, %1}, [%2];" : "=l"(a), "=l"(b) : "l"(p));
}

// =====================================================================
// K0: build X, init h row 0 + flags (block t clears flag row t+1)
// =====================================================================
__global__ void prep_kernel(const int* __restrict__ captions,
                            const float* __restrict__ features,
                            const float* __restrict__ etab) {
    int t = blockIdx.x;
    const float* src = (t == 0) ? features : (etab + (size_t)captions[t - 1] * E_DIM);
    for (int k = threadIdx.x; k < E_DIM; k += blockDim.x)
        g_X[t * E_DIM + k] = src[k];
    if (threadIdx.x < NBLK) g_hflag[(t + 1) * NBLK + threadIdx.x] = 0u;
    if (t == 0) {
        for (int k = threadIdx.x; k < H_DIM; k += blockDim.x) g_hpub[k] = 0.f;
        if (threadIdx.x < NBLK) g_hflag[threadIdx.x] = 1u;
    }
}

// =====================================================================
// K1: persistent LSTM — overlapped flag-wave barrier + f32x2 FMA.
// Block b owns h indices [8b, 8b+8). Thread: j=tid&7, c=tid>>3.
// Per step: all compute -> sync1 -> warp0 reduce -> sync2 ->
//   {warp0: activations+publish+release flag} || {warps1-4: poll 128 flags}
//   -> sync3.
// =====================================================================
__global__ void __launch_bounds__(512, 1)
lstm_kernel(const float* __restrict__ Wih, const float* __restrict__ Whh,
            const float* __restrict__ bih, const float* __restrict__ bhh) {
    __shared__ float Xg_s[T_STEPS * 32];   // [t][g*8+j]
    __shared__ float partA[16][32];        // [warp][g*8+j]
    __shared__ float gsum_s[32];
    __shared__ float bias_s[32];

    const int tid = threadIdx.x;
    const int w   = tid >> 5;
    const int l   = tid & 31;
    const int j   = tid & 7;
    const int c   = tid >> 3;     // 0..63
    const int b   = blockIdx.x;
    const int jg  = b * 8 + j;

    if (tid < 32) {
        int g = tid >> 3, jj = tid & 7;
        int row = g * H_DIM + b * 8 + jj;
        bias_s[tid] = bih[row] + bhh[row];
    }
    float creg = 0.f;              // cell state (valid for tid < 8)

    unsigned long long wreg2[4][8];   // 4 gates x 8 packed pairs (16 floats)

    // ---- load W_ih slice (packed) ----
#pragma unroll
    for (int g = 0; g < 4; g++) {
        const char* p = (const char*)(Wih + (size_t)(g * H_DIM + jg) * E_DIM + c * 16);
#pragma unroll
        for (int q = 0; q < 4; q++)
            ld2u64(p + q * 16, wreg2[g][2*q], wreg2[g][2*q+1]);
    }
    __syncthreads();

    // ---- Phase A: input projections ----
    for (int t = 0; t < T_STEPS; t++) {
        unsigned long long xv2[8];
        {
            const char* xp = (const char*)(g_X + t * E_DIM + c * 16);
#pragma unroll
            for (int q = 0; q < 4; q++)
                ld2u64(xp + q * 16, xv2[2*q], xv2[2*q+1]);
        }
        float part[4];
#pragma unroll
        for (int g = 0; g < 4; g++) {
            unsigned long long acc = 0ull;
#pragma unroll
            for (int i = 0; i < 8; i++) fma2(acc, wreg2[g][i], xv2[i]);
            part[g] = sum2(acc);
        }
#pragma unroll
        for (int g = 0; g < 4; g++) {
            part[g] += __shfl_xor_sync(0xffffffffu, part[g], 8);
            part[g] += __shfl_xor_sync(0xffffffffu, part[g], 16);
        }
        if (l < 8) {
#pragma unroll
            for (int g = 0; g < 4; g++) partA[w][g * 8 + l] = part[g];
        }
        __syncthreads();
        if (tid < 32) {
            float s = 0.f;
#pragma unroll
            for (int ww = 0; ww < 16; ww++) s += partA[ww][tid];
            Xg_s[t * 32 + tid] = s;
        }
        __syncthreads();
    }

    // ---- swap to W_hh slice (packed) ----
#pragma unroll
    for (int g = 0; g < 4; g++) {
        const char* p = (const char*)(Whh + (size_t)(g * H_DIM + jg) * H_DIM + c * 16);
#pragma unroll
        for (int q = 0; q < 4; q++)
            ld2u64(p + q * 16, wreg2[g][2*q], wreg2[g][2*q+1]);
    }
    __syncthreads();

    // ---- Phase B: recurrence ----
    for (int t = 0; t < T_STEPS; t++) {
        // h_t row is ready: guaranteed by previous iteration's poll + sync3
        unsigned long long hv2[8];
        {
            const char* hp = (const char*)(g_hpub + t * H_DIM + c * 16);
#pragma unroll
            for (int q = 0; q < 4; q++)
                ld2u64_cg(hp + q * 16, hv2[2*q], hv2[2*q+1]);
        }
        float part[4];
#pragma unroll
        for (int g = 0; g < 4; g++) {
            unsigned long long acc = 0ull;
#pragma unroll
            for (int i = 0; i < 8; i++) fma2(acc, wreg2[g][i], hv2[i]);
            part[g] = sum2(acc);
        }
#pragma unroll
        for (int g = 0; g < 4; g++) {
            part[g] += __shfl_xor_sync(0xffffffffu, part[g], 8);
            part[g] += __shfl_xor_sync(0xffffffffu, part[g], 16);
        }
        if (l < 8) {
#pragma unroll
            for (int g = 0; g < 4; g++) partA[w][g * 8 + l] = part[g];
        }
        __syncthreads();                       // sync1
        if (tid < 32) {
            float s = 0.f;
#pragma unroll
            for (int ww = 0; ww < 16; ww++) s += partA[ww][tid];
            gsum_s[tid] = s + Xg_s[t * 32 + tid] + bias_s[tid];
        }
        __syncthreads();                       // sync2

        // warp 0: activations + publish h_{t+1} + release flag
        if (tid < 8) {
            float ii = sigmoidf_(gsum_s[tid]);
            float ff = sigmoidf_(gsum_s[8  + tid]);
            float gg = tanhf_   (gsum_s[16 + tid]);
            float oo = sigmoidf_(gsum_s[24 + tid]);
            float cc = ff * creg + ii * gg;
            creg = cc;
            float hn = oo * tanhf_(cc);

            float vv[8];
#pragma unroll
            for (int i = 0; i < 8; i++)
                vv[i] = __shfl_sync(0x000000FFu, hn, i, 8);
            if (tid == 0) {
                float4* dst = (float4*)(g_hpub + (t + 1) * H_DIM + b * 8);
                dst[0] = make_float4(vv[0], vv[1], vv[2], vv[3]);
                dst[1] = make_float4(vv[4], vv[5], vv[6], vv[7]);
                // release: orders the two h stores before the flag
                asm volatile("st.release.gpu.u32 [%0], %1;"
                             :: "l"(&g_hflag[(t + 1) * NBLK + b]), "r"(1u) : "memory");
            }
        }
        // warps 1-4 (128 threads): poll all 128 flags of row t+1, one each.
        // Overlaps warp 0's tail. Skip on the last step (no next read).
        if (t < T_STEPS - 1 && tid >= 32 && tid < 160) {
            const unsigned int* fl = &g_hflag[(t + 1) * NBLK + (tid - 32)];
            unsigned int v;
            do {
                asm volatile("ld.acquire.gpu.u32 %0, [%1];"
                             : "=r"(v) : "l"(fl) : "memory");
            } while (!v);
        }
        __syncthreads();                       // sync3
    }
}

// =====================================================================
// K2: fc GEMM — fused convert + bf16 mma.sync 3-pass split (round-5 core).
// B tile reads g_hpub rows 1..64.
// =====================================================================
#define FC_M    128
#define FC_NCH  16

#define FCO_AF32(b) ((b) * 32768)
#define FCO_AHI     65536
#define FCO_ALO     81920
#define FCO_BHI     98304
#define FCO_BLO     106496
#define FC_SMEM     114688      // 112 KB -> 2 CTAs/SM

#define SWZ(x) ((x) ^ (((x) >> 3) & 0x70))

__device__ __forceinline__ uint32_t smem_u32(const void* p) {
    uint32_t a;
    asm("{ .reg .u64 t; cvta.to.shared.u64 t, %1; cvt.u32.u64 %0, t; }" : "=r"(a) : "l"(p));
    return a;
}

__device__ __forceinline__ void split2(float2 a, uint32_t& hi, uint32_t& lo) {
    __nv_bfloat162 h = __float22bfloat162_rn(a);
    float2 f = __bfloat1622float2(h);
    __nv_bfloat162 l2 = __float22bfloat162_rn(make_float2(a.x - f.x, a.y - f.y));
    hi = *reinterpret_cast<uint32_t*>(&h);
    lo = *reinterpret_cast<uint32_t*>(&l2);
}

#define CP16(dst, src) \
    asm volatile("cp.async.cg.shared.global [%0], [%1], 16;" :: "r"(dst), "l"(src) : "memory")
#define CP_COMMIT() asm volatile("cp.async.commit_group;" ::: "memory")
#define CP_WAIT(n)  asm volatile("cp.async.wait_group %0;" :: "n"(n) : "memory")

#define LDM_X4(r, a)                                                          \
    asm volatile("ldmatrix.sync.aligned.m8n8.x4.shared.b16 {%0,%1,%2,%3}, [%4];" \
        : "=r"((r)[0]), "=r"((r)[1]), "=r"((r)[2]), "=r"((r)[3]) : "r"(a))

#define MMA16816(d, a, b0, b1)                                                \
    asm volatile("mma.sync.aligned.m16n8k16.row.col.f32.bf16.bf16.f32 "       \
        "{%0,%1,%2,%3},{%4,%5,%6,%7},{%8,%9},{%0,%1,%2,%3};"                  \
        : "+f"((d)[0]), "+f"((d)[1]), "+f"((d)[2]), "+f"((d)[3])              \
        : "r"((a)[0]), "r"((a)[1]), "r"((a)[2]), "r"((a)[3]),                 \
          "r"(b0), "r"(b1))

__global__ void __launch_bounds__(128, 2)
fc_mma_kernel(const float* __restrict__ fcW, const float* __restrict__ fcb,
              float* __restrict__ out) {
    extern __shared__ __align__(1024) char smem[];
    const uint32_t sb = smem_u32(smem);

    const int tid  = threadIdx.x;
    const int wid  = tid >> 5;
    const int lane = tid & 31;
    const int vbase = blockIdx.x * FC_M;
    const int m0 = wid * 32;

    const int a_row  = m0 + (lane & 15);
    const uint32_t a_roff = (uint32_t)a_row * 128;
    const uint32_t a_xor  = (uint32_t)(a_row & 7) << 4;
    const uint32_t a_kh   = (uint32_t)(lane >> 4) * 16;
    const int b_rsub = (lane & 7) + ((lane >> 4) & 1) * 8;
    const uint32_t b_xor = (uint32_t)(lane & 7) << 4;
    const uint32_t b_kh  = (uint32_t)((lane >> 3) & 1) * 16;

    float acc[2][8][4];
#pragma unroll
    for (int mt = 0; mt < 2; mt++)
#pragma unroll
        for (int nt = 0; nt < 8; nt++)
#pragma unroll
            for (int q = 0; q < 4; q++) acc[mt][nt][q] = 0.f;

    auto issue = [&](int c) {
        const uint32_t dbase = sb + FCO_AF32(c & 1);
#pragma unroll
        for (int p = 0; p < 16; p++) {
            int idx = tid + p * 128;
            int row = idx >> 4, seg = idx & 15;
            const char* src = (const char*)(fcW + (size_t)(vbase + row) * E_DIM + c * 64)
                              + seg * 16;
            CP16(dbase + (uint32_t)(row * 256 + seg * 16), src);
        }
        CP_COMMIT();
    };

    issue(0);
    issue(1);

    for (int c = 0; c < FC_NCH; c++) {
        if (c < FC_NCH - 1) { CP_WAIT(1); } else { CP_WAIT(0); }
        __syncthreads();

        {
            const char* af = smem + FCO_AF32(c & 1);
#pragma unroll
            for (int p = 0; p < 32; p++) {
                int fidx = tid + p * 128;
                int row = fidx >> 5, kp = fidx & 31;
                float2 a = *(const float2*)(af + row * 256 + kp * 8);
                uint32_t hi, lo; split2(a, hi, lo);
                uint32_t off = SWZ((uint32_t)(row * 128 + kp * 4));
                *(uint32_t*)(smem + FCO_AHI + off) = hi;
                *(uint32_t*)(smem + FCO_ALO + off) = lo;
            }
        }
        {
#pragma unroll
            for (int p = 0; p < 16; p++) {
                int fidx = tid + p * 128;
                int row = fidx >> 5, kp = fidx & 31;
                float2 a = *(const float2*)(g_hpub + (row + 1) * H_DIM + c * 64 + kp * 2);
                uint32_t hi, lo; split2(a, hi, lo);
                uint32_t off = SWZ((uint32_t)(row * 128 + kp * 4));
                *(uint32_t*)(smem + FCO_BHI + off) = hi;
                *(uint32_t*)(smem + FCO_BLO + off) = lo;
            }
        }
        __syncthreads();

        if (c + 2 < FC_NCH) issue(c + 2);

        const uint32_t sAhi = sb + FCO_AHI, sAlo = sb + FCO_ALO;
        const uint32_t sBhi = sb + FCO_BHI, sBlo = sb + FCO_BLO;
#pragma unroll
        for (int ks = 0; ks < 4; ks++) {
            const uint32_t akb = (uint32_t)(ks * 32) + a_kh;
            const uint32_t bkb = (uint32_t)(ks * 32) + b_kh;

            uint32_t ah[2][4], al[2][4];
#pragma unroll
            for (int mt = 0; mt < 2; mt++) {
                uint32_t off = a_roff + (uint32_t)(mt * 16 * 128) + (akb ^ a_xor);
                LDM_X4(ah[mt], sAhi + off);
                LDM_X4(al[mt], sAlo + off);
            }
            uint32_t bh[4][4], bl[4][4];
#pragma unroll
            for (int bp = 0; bp < 4; bp++) {
                uint32_t n = (uint32_t)(bp * 16 + b_rsub);
                uint32_t off = n * 128 + (bkb ^ b_xor);
                LDM_X4(bh[bp], sBhi + off);
                LDM_X4(bl[bp], sBlo + off);
            }
#pragma unroll
            for (int mt = 0; mt < 2; mt++)
#pragma unroll
                for (int nt = 0; nt < 8; nt++) {
                    const int bp = nt >> 1, sel = (nt & 1) * 2;
                    MMA16816(acc[mt][nt], ah[mt], bh[bp][sel], bh[bp][sel + 1]);
                    MMA16816(acc[mt][nt], al[mt], bh[bp][sel], bh[bp][sel + 1]);
                    MMA16816(acc[mt][nt], ah[mt], bl[bp][sel], bl[bp][sel + 1]);
                }
        }
    }

    const int g  = lane >> 2;
    const int t4 = lane & 3;
#pragma unroll
    for (int mt = 0; mt < 2; mt++) {
        int v0 = vbase + m0 + mt * 16 + g;
        float bv0 = fcb[v0];
        float bv8 = fcb[v0 + 8];
#pragma unroll
        for (int nt = 0; nt < 8; nt++) {
            int t0 = nt * 8 + t4 * 2;
            out[(size_t)t0 * VOC + v0]           = acc[mt][nt][0] + bv0;
            out[(size_t)(t0 + 1) * VOC + v0]     = acc[mt][nt][1] + bv0;
            out[(size_t)t0 * VOC + v0 + 8]       = acc[mt][nt][2] + bv8;
            out[(size_t)(t0 + 1) * VOC + v0 + 8] = acc[mt][nt][3] + bv8;
        }
    }
}

// =====================================================================
// launch
// =====================================================================
extern "C" void kernel_launch(void* const* d_in, const int* in_sizes, int n_in,
                              void* d_out, int out_size) {
    const int*   captions = (const int*)  d_in[0];
    const float* features = (const float*)d_in[1];
    const float* etab     = (const float*)d_in[2];
    const float* W_ih     = (const float*)d_in[3];
    const float* W_hh     = (const float*)d_in[4];
    const float* b_ih     = (const float*)d_in[5];
    const float* b_hh     = (const float*)d_in[6];
    const float* fc_W     = (const float*)d_in[7];
    const float* fc_b     = (const float*)d_in[8];
    float* out = (float*)d_out;

    cudaFuncSetAttribute(fc_mma_kernel,
                         cudaFuncAttributeMaxDynamicSharedMemorySize, FC_SMEM);

    prep_kernel<<<T_STEPS, 256>>>(captions, features, etab);
    lstm_kernel<<<NBLK, 512>>>(W_ih, W_hh, b_ih, b_hh);
    fc_mma_kernel<<<VOC / FC_M, 128, FC_SMEM>>>(fc_W, fc_b, out);
}

// round 9
// speedup vs baseline: 3.4946x; 2.6445x over previous
#include <cuda_runtime.h>
#include <cuda_bf16.h>
#include <cstdint>
#include <cstdio>

#define E_DIM 1024
#define H_DIM 1024
#define VOC   32000
#define T_STEPS 64
#define NBLK  128          // persistent LSTM blocks

// -------- device scratch (no allocs allowed) --------
__device__ float g_X[T_STEPS * E_DIM];              // inputs per step
__device__ float g_hpub[(T_STEPS + 1) * H_DIM];     // fresh h row per step
__device__ unsigned int g_cnt;                      // single barrier counter

__device__ __forceinline__ float sigmoidf_(float x) { return 1.f / (1.f + __expf(-x)); }
__device__ __forceinline__ float tanhf_(float x) {
    return __fdividef(2.f, 1.f + __expf(-2.f * x)) - 1.f;
}

// ---- packed f32x2 helpers ----
__device__ __forceinline__ void fma2(unsigned long long& d,
                                     unsigned long long a, unsigned long long b) {
    asm("fma.rn.f32x2 %0, %1, %2, %0;" : "+l"(d) : "l"(a), "l"(b));
}
__device__ __forceinline__ float sum2(unsigned long long v) {
    float lo, hi;
    asm("mov.b64 {%0, %1}, %2;" : "=f"(lo), "=f"(hi) : "l"(v));
    return lo + hi;
}
__device__ __forceinline__ void ld2u64(const void* p, unsigned long long& a,
                                       unsigned long long& b) {
    asm("ld.global.v2.u64 {%0, %1}, [%2];" : "=l"(a), "=l"(b) : "l"(p));
}
__device__ __forceinline__ void ld2u64_cg(const void* p, unsigned long long& a,
                                          unsigned long long& b) {
    asm("ld.global.cg.v2.u64 {%0, %1}, [%2];" : "=l"(a), "=l"(b) : "l"(p));
}

// =====================================================================
// K0: build X, init h row 0 + counter
// =====================================================================
__global__ void prep_kernel(const int* __restrict__ captions,
                            const float* __restrict__ features,
                            const float* __restrict__ etab) {
    int t = blockIdx.x;
    const float* src = (t == 0) ? features : (etab + (size_t)captions[t - 1] * E_DIM);
    for (int k = threadIdx.x; k < E_DIM; k += blockDim.x)
        g_X[t * E_DIM + k] = src[k];
    if (t == 0) {
        for (int k = threadIdx.x; k < H_DIM; k += blockDim.x) g_hpub[k] = 0.f;
        if (threadIdx.x == 0) g_cnt = 0u;
    }
}

// =====================================================================
// K1: persistent LSTM — R3 skeleton, slimmed critical path.
// Block b owns h indices [8b, 8b+8). Thread: j=tid&7, c=tid>>3.
// Per step: compute -> sync1 -> warp0 {reduce, shfl-activations, publish,
//   red.release, tid0 poll} -> sync_final.
// =====================================================================
__global__ void __launch_bounds__(512, 1)
lstm_kernel(const float* __restrict__ Wih, const float* __restrict__ Whh,
            const float* __restrict__ bih, const float* __restrict__ bhh) {
    __shared__ float Xg_s[T_STEPS * 32];   // [t][g*8+j]
    __shared__ float partA[16][32];        // [warp][g*8+j]
    __shared__ float bias_s[32];

    const int tid = threadIdx.x;
    const int w   = tid >> 5;
    const int l   = tid & 31;
    const int j   = tid & 7;
    const int c   = tid >> 3;     // 0..63
    const int b   = blockIdx.x;
    const int jg  = b * 8 + j;

    if (tid < 32) {
        int g = tid >> 3, jj = tid & 7;
        int row = g * H_DIM + b * 8 + jj;
        bias_s[tid] = bih[row] + bhh[row];
    }
    float creg = 0.f;                 // cell state (tid < 8)

    unsigned long long wreg2[4][8];   // 4 gates x 16 floats packed

    // ---- W_ih slice ----
#pragma unroll
    for (int g = 0; g < 4; g++) {
        const char* p = (const char*)(Wih + (size_t)(g * H_DIM + jg) * E_DIM + c * 16);
#pragma unroll
        for (int q = 0; q < 4; q++)
            ld2u64(p + q * 16, wreg2[g][2*q], wreg2[g][2*q+1]);
    }
    __syncthreads();

    // ---- Phase A: input projections ----
    for (int t = 0; t < T_STEPS; t++) {
        unsigned long long xv2[8];
        {
            const char* xp = (const char*)(g_X + t * E_DIM + c * 16);
#pragma unroll
            for (int q = 0; q < 4; q++)
                ld2u64(xp + q * 16, xv2[2*q], xv2[2*q+1]);
        }
        float part[4];
#pragma unroll
        for (int g = 0; g < 4; g++) {
            unsigned long long acc = 0ull;
#pragma unroll
            for (int i = 0; i < 8; i++) fma2(acc, wreg2[g][i], xv2[i]);
            part[g] = sum2(acc);
        }
#pragma unroll
        for (int g = 0; g < 4; g++) {
            part[g] += __shfl_xor_sync(0xffffffffu, part[g], 8);
            part[g] += __shfl_xor_sync(0xffffffffu, part[g], 16);
        }
        if (l < 8) {
#pragma unroll
            for (int g = 0; g < 4; g++) partA[w][g * 8 + l] = part[g];
        }
        __syncthreads();
        if (tid < 32) {
            float s = 0.f;
#pragma unroll
            for (int ww = 0; ww < 16; ww++) s += partA[ww][tid];
            Xg_s[t * 32 + tid] = s;
        }
        __syncthreads();
    }

    // ---- W_hh slice ----
#pragma unroll
    for (int g = 0; g < 4; g++) {
        const char* p = (const char*)(Whh + (size_t)(g * H_DIM + jg) * H_DIM + c * 16);
#pragma unroll
        for (int q = 0; q < 4; q++)
            ld2u64(p + q * 16, wreg2[g][2*q], wreg2[g][2*q+1]);
    }
    __syncthreads();

    // ---- Phase B: recurrence ----
    for (int t = 0; t < T_STEPS; t++) {
        // h row t guaranteed ready by previous step's barrier
        unsigned long long hv2[8];
        {
            const char* hp = (const char*)(g_hpub + t * H_DIM + c * 16);
#pragma unroll
            for (int q = 0; q < 4; q++)
                ld2u64_cg(hp + q * 16, hv2[2*q], hv2[2*q+1]);
        }
        float part[4];
#pragma unroll
        for (int g = 0; g < 4; g++) {
            unsigned long long acc = 0ull;
#pragma unroll
            for (int i = 0; i < 8; i++) fma2(acc, wreg2[g][i], hv2[i]);
            part[g] = sum2(acc);
        }
#pragma unroll
        for (int g = 0; g < 4; g++) {
            part[g] += __shfl_xor_sync(0xffffffffu, part[g], 8);
            part[g] += __shfl_xor_sync(0xffffffffu, part[g], 16);
        }
        if (l < 8) {
#pragma unroll
            for (int g = 0; g < 4; g++) partA[w][g * 8 + l] = part[g];
        }
        __syncthreads();                          // sync1

        if (tid < 32) {
            // final reduce in registers (warp 0 only)
            float s = bias_s[tid] + Xg_s[t * 32 + tid];
#pragma unroll
            for (int ww = 0; ww < 16; ww++) s += partA[ww][tid];

            // fetch the 4 gate values for h-index (tid&7) via shfl.idx
            const int jj = tid & 7;
            float sf = __shfl_sync(0xffffffffu, s, jj + 8);
            float sg = __shfl_sync(0xffffffffu, s, jj + 16);
            float so = __shfl_sync(0xffffffffu, s, jj + 24);

            if (tid < 8) {
                float ii = sigmoidf_(s);
                float ff = sigmoidf_(sf);
                float gg = tanhf_(sg);
                float oo = sigmoidf_(so);
                float cc = ff * creg + ii * gg;
                creg = cc;
                float hn = oo * tanhf_(cc);

                float vv[8];
#pragma unroll
                for (int i = 0; i < 8; i++)
                    vv[i] = __shfl_sync(0x000000FFu, hn, i, 8);
                if (tid == 0) {
                    float4* dst = (float4*)(g_hpub + (t + 1) * H_DIM + b * 8);
                    dst[0] = make_float4(vv[0], vv[1], vv[2], vv[3]);
                    dst[1] = make_float4(vv[4], vv[5], vv[6], vv[7]);
                    // release-arrival: orders the two h stores (same thread)
                    asm volatile("red.release.gpu.global.add.u32 [%0], 1;"
                                 :: "l"(&g_cnt) : "memory");
                }
            }
            if (tid == 0) {
                const unsigned int target = (unsigned)NBLK * (unsigned)(t + 1);
                unsigned int v;
                do {
                    asm volatile("ld.acquire.gpu.u32 %0, [%1];"
                                 : "=r"(v) : "l"(&g_cnt) : "memory");
                } while (v < target);
            }
        }
        __syncthreads();                          // sync_final
    }
}

// =====================================================================
// K2: fc GEMM — fused convert + bf16 mma.sync 3-pass split (round-5 core).
// B tile reads g_hpub rows 1..64.
// =====================================================================
#define FC_M    128
#define FC_NCH  16

#define FCO_AF32(b) ((b) * 32768)
#define FCO_AHI     65536
#define FCO_ALO     81920
#define FCO_BHI     98304
#define FCO_BLO     106496
#define FC_SMEM     114688      // 112 KB -> 2 CTAs/SM

#define SWZ(x) ((x) ^ (((x) >> 3) & 0x70))

__device__ __forceinline__ uint32_t smem_u32(const void* p) {
    uint32_t a;
    asm("{ .reg .u64 t; cvta.to.shared.u64 t, %1; cvt.u32.u64 %0, t; }" : "=r"(a) : "l"(p));
    return a;
}

__device__ __forceinline__ void split2(float2 a, uint32_t& hi, uint32_t& lo) {
    __nv_bfloat162 h = __float22bfloat162_rn(a);
    float2 f = __bfloat1622float2(h);
    __nv_bfloat162 l2 = __float22bfloat162_rn(make_float2(a.x - f.x, a.y - f.y));
    hi = *reinterpret_cast<uint32_t*>(&h);
    lo = *reinterpret_cast<uint32_t*>(&l2);
}

#define CP16(dst, src) \
    asm volatile("cp.async.cg.shared.global [%0], [%1], 16;" :: "r"(dst), "l"(src) : "memory")
#define CP_COMMIT() asm volatile("cp.async.commit_group;" ::: "memory")
#define CP_WAIT(n)  asm volatile("cp.async.wait_group %0;" :: "n"(n) : "memory")

#define LDM_X4(r, a)                                                          \
    asm volatile("ldmatrix.sync.aligned.m8n8.x4.shared.b16 {%0,%1,%2,%3}, [%4];" \
        : "=r"((r)[0]), "=r"((r)[1]), "=r"((r)[2]), "=r"((r)[3]) : "r"(a))

#define MMA16816(d, a, b0, b1)                                                \
    asm volatile("mma.sync.aligned.m16n8k16.row.col.f32.bf16.bf16.f32 "       \
        "{%0,%1,%2,%3},{%4,%5,%6,%7},{%8,%9},{%0,%1,%2,%3};"                  \
        : "+f"((d)[0]), "+f"((d)[1]), "+f"((d)[2]), "+f"((d)[3])              \
        : "r"((a)[0]), "r"((a)[1]), "r"((a)[2]), "r"((a)[3]),                 \
          "r"(b0), "r"(b1))

__global__ void __launch_bounds__(128, 2)
fc_mma_kernel(const float* __restrict__ fcW, const float* __restrict__ fcb,
              float* __restrict__ out) {
    extern __shared__ __align__(1024) char smem[];
    const uint32_t sb = smem_u32(smem);

    const int tid  = threadIdx.x;
    const int wid  = tid >> 5;
    const int lane = tid & 31;
    const int vbase = blockIdx.x * FC_M;
    const int m0 = wid * 32;

    const int a_row  = m0 + (lane & 15);
    const uint32_t a_roff = (uint32_t)a_row * 128;
    const uint32_t a_xor  = (uint32_t)(a_row & 7) << 4;
    const uint32_t a_kh   = (uint32_t)(lane >> 4) * 16;
    const int b_rsub = (lane & 7) + ((lane >> 4) & 1) * 8;
    const uint32_t b_xor = (uint32_t)(lane & 7) << 4;
    const uint32_t b_kh  = (uint32_t)((lane >> 3) & 1) * 16;

    float acc[2][8][4];
#pragma unroll
    for (int mt = 0; mt < 2; mt++)
#pragma unroll
        for (int nt = 0; nt < 8; nt++)
#pragma unroll
            for (int q = 0; q < 4; q++) acc[mt][nt][q] = 0.f;

    auto issue = [&](int c) {
        const uint32_t dbase = sb + FCO_AF32(c & 1);
#pragma unroll
        for (int p = 0; p < 16; p++) {
            int idx = tid + p * 128;
            int row = idx >> 4, seg = idx & 15;
            const char* src = (const char*)(fcW + (size_t)(vbase + row) * E_DIM + c * 64)
                              + seg * 16;
            CP16(dbase + (uint32_t)(row * 256 + seg * 16), src);
        }
        CP_COMMIT();
    };

    issue(0);
    issue(1);

    for (int c = 0; c < FC_NCH; c++) {
        if (c < FC_NCH - 1) { CP_WAIT(1); } else { CP_WAIT(0); }
        __syncthreads();

        {
            const char* af = smem + FCO_AF32(c & 1);
#pragma unroll
            for (int p = 0; p < 32; p++) {
                int fidx = tid + p * 128;
                int row = fidx >> 5, kp = fidx & 31;
                float2 a = *(const float2*)(af + row * 256 + kp * 8);
                uint32_t hi, lo; split2(a, hi, lo);
                uint32_t off = SWZ((uint32_t)(row * 128 + kp * 4));
                *(uint32_t*)(smem + FCO_AHI + off) = hi;
                *(uint32_t*)(smem + FCO_ALO + off) = lo;
            }
        }
        {
#pragma unroll
            for (int p = 0; p < 16; p++) {
                int fidx = tid + p * 128;
                int row = fidx >> 5, kp = fidx & 31;
                float2 a = *(const float2*)(g_hpub + (row + 1) * H_DIM + c * 64 + kp * 2);
                uint32_t hi, lo; split2(a, hi, lo);
                uint32_t off = SWZ((uint32_t)(row * 128 + kp * 4));
                *(uint32_t*)(smem + FCO_BHI + off) = hi;
                *(uint32_t*)(smem + FCO_BLO + off) = lo;
            }
        }
        __syncthreads();

        if (c + 2 < FC_NCH) issue(c + 2);

        const uint32_t sAhi = sb + FCO_AHI, sAlo = sb + FCO_ALO;
        const uint32_t sBhi = sb + FCO_BHI, sBlo = sb + FCO_BLO;
#pragma unroll
        for (int ks = 0; ks < 4; ks++) {
            const uint32_t akb = (uint32_t)(ks * 32) + a_kh;
            const uint32_t bkb = (uint32_t)(ks * 32) + b_kh;

            uint32_t ah[2][4], al[2][4];
#pragma unroll
            for (int mt = 0; mt < 2; mt++) {
                uint32_t off = a_roff + (uint32_t)(mt * 16 * 128) + (akb ^ a_xor);
                LDM_X4(ah[mt], sAhi + off);
                LDM_X4(al[mt], sAlo + off);
            }
            uint32_t bh[4][4], bl[4][4];
#pragma unroll
            for (int bp = 0; bp < 4; bp++) {
                uint32_t n = (uint32_t)(bp * 16 + b_rsub);
                uint32_t off = n * 128 + (bkb ^ b_xor);
                LDM_X4(bh[bp], sBhi + off);
                LDM_X4(bl[bp], sBlo + off);
            }
#pragma unroll
            for (int mt = 0; mt < 2; mt++)
#pragma unroll
                for (int nt = 0; nt < 8; nt++) {
                    const int bp = nt >> 1, sel = (nt & 1) * 2;
                    MMA16816(acc[mt][nt], ah[mt], bh[bp][sel], bh[bp][sel + 1]);
                    MMA16816(acc[mt][nt], al[mt], bh[bp][sel], bh[bp][sel + 1]);
                    MMA16816(acc[mt][nt], ah[mt], bl[bp][sel], bl[bp][sel + 1]);
                }
        }
    }

    const int g  = lane >> 2;
    const int t4 = lane & 3;
#pragma unroll
    for (int mt = 0; mt < 2; mt++) {
        int v0 = vbase + m0 + mt * 16 + g;
        float bv0 = fcb[v0];
        float bv8 = fcb[v0 + 8];
#pragma unroll
        for (int nt = 0; nt < 8; nt++) {
            int t0 = nt * 8 + t4 * 2;
            out[(size_t)t0 * VOC + v0]           = acc[mt][nt][0] + bv0;
            out[(size_t)(t0 + 1) * VOC + v0]     = acc[mt][nt][1] + bv0;
            out[(size_t)t0 * VOC + v0 + 8]       = acc[mt][nt][2] + bv8;
            out[(size_t)(t0 + 1) * VOC + v0 + 8] = acc[mt][nt][3] + bv8;
        }
    }
}

// =====================================================================
// launch
// =====================================================================
extern "C" void kernel_launch(void* const* d_in, const int* in_sizes, int n_in,
                              void* d_out, int out_size) {
    const int*   captions = (const int*)  d_in[0];
    const float* features = (const float*)d_in[1];
    const float* etab     = (const float*)d_in[2];
    const float* W_ih     = (const float*)d_in[3];
    const float* W_hh     = (const float*)d_in[4];
    const float* b_ih     = (const float*)d_in[5];
    const float* b_hh     = (const float*)d_in[6];
    const float* fc_W     = (const float*)d_in[7];
    const float* fc_b     = (const float*)d_in[8];
    float* out = (float*)d_out;

    cudaFuncSetAttribute(fc_mma_kernel,
                         cudaFuncAttributeMaxDynamicSharedMemorySize, FC_SMEM);

    prep_kernel<<<T_STEPS, 256>>>(captions, features, etab);
    lstm_kernel<<<NBLK, 512>>>(W_ih, W_hh, b_ih, b_hh);
    fc_mma_kernel<<<VOC / FC_M, 128, FC_SMEM>>>(fc_W, fc_b, out);
}